// round 1
// baseline (speedup 1.0000x reference)
#include <cuda_runtime.h>
#include <cuda_bf16.h>

// Problem constants
#define BB   4
#define NN   2048
#define DIM  1024
#define HEADS 16
#define DH   64
#define INNER 1024          // HEADS*DH
#define QKVC 3072           // 3*INNER
#define MROWS (BB*NN)       // 8192

// Scratch for qkv = x @ w_qkv   [8192, 3072] fp32
__device__ float g_qkv[(long)MROWS * QKVC];

// ---------------------------------------------------------------------------
// Kernel 1: QKV projection GEMM  C[M,3072] = A[M,1024] @ W[1024,3072]
// classic 128x128x8 tile, 256 threads, 8x8 per-thread micro-tile
// ---------------------------------------------------------------------------
__global__ __launch_bounds__(256) void qkv_gemm(const float* __restrict__ A,
                                                const float* __restrict__ W) {
    const int M = MROWS, N = QKVC, K = DIM;
    __shared__ float As[8][128];   // transposed A tile
    __shared__ float Bs[8][128];

    int tid = threadIdx.x;
    int bx = blockIdx.x;           // N tile
    int by = blockIdx.y;           // M tile

    int arow = tid >> 1;           // 0..127
    int acol = (tid & 1) * 4;      // 0 or 4
    int brow = tid >> 5;           // 0..7
    int bcol = (tid & 31) * 4;     // 0..124

    int tx = tid & 15;             // col group
    int ty = tid >> 4;             // row group

    const float* Ab = A + (long)(by * 128) * K;
    const float* Bb = W + bx * 128;

    float c[8][8];
#pragma unroll
    for (int i = 0; i < 8; i++)
#pragma unroll
        for (int j = 0; j < 8; j++) c[i][j] = 0.f;

    for (int k0 = 0; k0 < K; k0 += 8) {
        float4 a4 = *(const float4*)&Ab[(long)arow * K + k0 + acol];
        As[acol + 0][arow] = a4.x;
        As[acol + 1][arow] = a4.y;
        As[acol + 2][arow] = a4.z;
        As[acol + 3][arow] = a4.w;
        float4 b4 = *(const float4*)&Bb[(long)(k0 + brow) * N + bcol];
        *(float4*)&Bs[brow][bcol] = b4;
        __syncthreads();
#pragma unroll
        for (int kk = 0; kk < 8; ++kk) {
            float a[8], b[8];
#pragma unroll
            for (int i = 0; i < 8; i++) a[i] = As[kk][ty * 8 + i];
#pragma unroll
            for (int j = 0; j < 8; j++) b[j] = Bs[kk][tx * 8 + j];
#pragma unroll
            for (int i = 0; i < 8; i++)
#pragma unroll
                for (int j = 0; j < 8; j++) c[i][j] += a[i] * b[j];
        }
        __syncthreads();
    }

    float* C = g_qkv + (long)(by * 128 + ty * 8) * N + bx * 128 + tx * 8;
#pragma unroll
    for (int i = 0; i < 8; i++) {
        *(float4*)&C[(long)i * N + 0] = make_float4(c[i][0], c[i][1], c[i][2], c[i][3]);
        *(float4*)&C[(long)i * N + 4] = make_float4(c[i][4], c[i][5], c[i][6], c[i][7]);
    }
}

// ---------------------------------------------------------------------------
// Kernel 2: flash attention fp32
// grid (N/64, HEADS, B), 256 threads. Each CTA: 64 query rows, stream K/V in
// 64-row tiles. Thread (tx,ty) owns 4 rows x 4 cols in both phases.
// ---------------------------------------------------------------------------
#define BR 64
#define BC 64
#define ST 65   // smem row stride (pad to kill bank conflicts)

__global__ __launch_bounds__(256) void attn_kernel(const float* __restrict__ qkv,
                                                   float* __restrict__ out) {
    extern __shared__ float sm[];
    float* Qs = sm;                 // [64][ST]
    float* Ks = sm + 64 * ST;
    float* Vs = sm + 2 * 64 * ST;
    float* Ps = sm + 3 * 64 * ST;

    const int i0 = blockIdx.x * BR;
    const int h  = blockIdx.y;
    const int b  = blockIdx.z;
    const int tid = threadIdx.x;
    const int tx = tid & 15;
    const int ty = tid >> 4;
    const int r0 = ty * 4;          // my 4 query rows
    const int j0 = tx * 4;          // my 4 key cols (score phase)
    const int d0 = tx * 4;          // my 4 head dims (AV phase)
    const float scale = 0.125f;     // 64^-0.5

    const long rowbase = (long)b * NN * QKVC;

    // Load Q tile (64x64), float4 global reads, scalar smem stores (ST is odd)
    for (int e = tid; e < 64 * 16; e += 256) {
        int r  = e >> 4;
        int c4 = (e & 15) * 4;
        float4 v = *(const float4*)&qkv[rowbase + (long)(i0 + r) * QKVC + h * DH + c4];
        Qs[r * ST + c4 + 0] = v.x;
        Qs[r * ST + c4 + 1] = v.y;
        Qs[r * ST + c4 + 2] = v.z;
        Qs[r * ST + c4 + 3] = v.w;
    }

    float m_i[4], l_i[4], acc[4][4];
#pragma unroll
    for (int i = 0; i < 4; i++) {
        m_i[i] = -1e30f;
        l_i[i] = 0.f;
#pragma unroll
        for (int j = 0; j < 4; j++) acc[i][j] = 0.f;
    }

    for (int t = 0; t < NN / BC; ++t) {
        __syncthreads();   // previous-iter smem consumers done
        // load K, V tiles
        for (int e = tid; e < 64 * 16; e += 256) {
            int r  = e >> 4;
            int c4 = (e & 15) * 4;
            long g = rowbase + (long)(t * BC + r) * QKVC + h * DH + c4;
            float4 kv = *(const float4*)&qkv[g + INNER];
            Ks[r * ST + c4 + 0] = kv.x;
            Ks[r * ST + c4 + 1] = kv.y;
            Ks[r * ST + c4 + 2] = kv.z;
            Ks[r * ST + c4 + 3] = kv.w;
            float4 vv = *(const float4*)&qkv[g + 2 * INNER];
            Vs[r * ST + c4 + 0] = vv.x;
            Vs[r * ST + c4 + 1] = vv.y;
            Vs[r * ST + c4 + 2] = vv.z;
            Vs[r * ST + c4 + 3] = vv.w;
        }
        __syncthreads();

        // S = Q K^T  (4x4 per thread)
        float s[4][4];
#pragma unroll
        for (int i = 0; i < 4; i++)
#pragma unroll
            for (int j = 0; j < 4; j++) s[i][j] = 0.f;

        for (int k = 0; k < DH; ++k) {
            float q[4], kk[4];
#pragma unroll
            for (int i = 0; i < 4; i++) q[i]  = Qs[(r0 + i) * ST + k];
#pragma unroll
            for (int j = 0; j < 4; j++) kk[j] = Ks[(j0 + j) * ST + k];
#pragma unroll
            for (int i = 0; i < 4; i++)
#pragma unroll
                for (int j = 0; j < 4; j++) s[i][j] += q[i] * kk[j];
        }

        // online softmax update per row
#pragma unroll
        for (int ri = 0; ri < 4; ++ri) {
            float mt = -1e30f;
#pragma unroll
            for (int ji = 0; ji < 4; ++ji) {
                s[ri][ji] *= scale;
                mt = fmaxf(mt, s[ri][ji]);
            }
            // reduce over the 16 tx-lanes (same ty group, within a warp half)
            mt = fmaxf(mt, __shfl_xor_sync(0xffffffffu, mt, 1));
            mt = fmaxf(mt, __shfl_xor_sync(0xffffffffu, mt, 2));
            mt = fmaxf(mt, __shfl_xor_sync(0xffffffffu, mt, 4));
            mt = fmaxf(mt, __shfl_xor_sync(0xffffffffu, mt, 8));
            float mnew = fmaxf(m_i[ri], mt);
            float corr = __expf(m_i[ri] - mnew);
            m_i[ri] = mnew;
            float ls = 0.f;
#pragma unroll
            for (int ji = 0; ji < 4; ++ji) {
                float p = __expf(s[ri][ji] - mnew);
                ls += p;
                Ps[(r0 + ri) * ST + j0 + ji] = p;
            }
            ls += __shfl_xor_sync(0xffffffffu, ls, 1);
            ls += __shfl_xor_sync(0xffffffffu, ls, 2);
            ls += __shfl_xor_sync(0xffffffffu, ls, 4);
            ls += __shfl_xor_sync(0xffffffffu, ls, 8);
            l_i[ri] = l_i[ri] * corr + ls;
#pragma unroll
            for (int di = 0; di < 4; ++di) acc[ri][di] *= corr;
        }
        __syncwarp();   // P rows owned by same-ty lanes of this warp only

        // O += P V  (4 rows x 4 dims per thread)
        for (int j = 0; j < BC; ++j) {
            float p[4], vv[4];
#pragma unroll
            for (int ri = 0; ri < 4; ++ri) p[ri]  = Ps[(r0 + ri) * ST + j];
#pragma unroll
            for (int di = 0; di < 4; ++di) vv[di] = Vs[j * ST + d0 + di];
#pragma unroll
            for (int ri = 0; ri < 4; ++ri)
#pragma unroll
                for (int di = 0; di < 4; ++di) acc[ri][di] += p[ri] * vv[di];
        }
    }

    // epilogue: normalize, write out[b, n, h*64 + d]
#pragma unroll
    for (int ri = 0; ri < 4; ++ri) {
        float inv = 1.f / l_i[ri];
        long obase = ((long)b * NN + i0 + r0 + ri) * INNER + h * DH + d0;
#pragma unroll
        for (int di = 0; di < 4; ++di)
            out[obase + di] = acc[ri][di] * inv;
    }
}

// ---------------------------------------------------------------------------
extern "C" void kernel_launch(void* const* d_in, const int* in_sizes, int n_in,
                              void* d_out, int out_size) {
    const float* x = (const float*)d_in[0];
    const float* w = (const float*)d_in[1];
    float* out = (float*)d_out;

    // GEMM: grid (3072/128, 8192/128)
    dim3 g1(QKVC / 128, MROWS / 128);
    qkv_gemm<<<g1, 256>>>(x, w);

    // Attention
    int smem = 4 * 64 * ST * (int)sizeof(float);  // 66560 B
    static int configured = 0;
    if (!configured) {
        cudaFuncSetAttribute(attn_kernel, cudaFuncAttributeMaxDynamicSharedMemorySize, smem);
        configured = 1;
    }
    float* qkv_ptr = nullptr;
    cudaGetSymbolAddress((void**)&qkv_ptr, g_qkv);
    dim3 g2(NN / BR, HEADS, BB);
    attn_kernel<<<g2, 256, smem>>>(qkv_ptr, out);
}

// round 2
// speedup vs baseline: 2.6119x; 2.6119x over previous
#include <cuda_runtime.h>
#include <cuda_bf16.h>
#include <mma.h>

using namespace nvcuda;

// Problem constants
#define BB   4
#define NN   2048
#define DIM  1024
#define HEADS 16
#define DH   64
#define INNER 1024          // HEADS*DH
#define QKVC 3072           // 3*INNER
#define MROWS (BB*NN)       // 8192

// Scratch for qkv = x @ w_qkv   [8192, 3072] fp32 (tf32-precision values)
__device__ float g_qkv[(long)MROWS * QKVC];

// ---------------------------------------------------------------------------
// helpers
// ---------------------------------------------------------------------------
__device__ __forceinline__ float to_tf32(float x) {
    unsigned u;
    asm("cvt.rna.tf32.f32 %0, %1;" : "=r"(u) : "f"(x));
    return __uint_as_float(u);
}

__device__ __forceinline__ void mma_tf32(float c[4],
                                         unsigned a0, unsigned a1, unsigned a2, unsigned a3,
                                         unsigned b0, unsigned b1) {
    asm volatile(
        "mma.sync.aligned.m16n8k8.row.col.f32.tf32.tf32.f32 "
        "{%0,%1,%2,%3}, {%4,%5,%6,%7}, {%8,%9}, {%0,%1,%2,%3};"
        : "+f"(c[0]), "+f"(c[1]), "+f"(c[2]), "+f"(c[3])
        : "r"(a0), "r"(a1), "r"(a2), "r"(a3), "r"(b0), "r"(b1));
}

// ---------------------------------------------------------------------------
// Kernel 1: QKV projection GEMM via wmma tf32.
// C[8192,3072] = A[8192,1024] @ W[1024,3072].
// CTA tile 128x128, BK=32, 8 warps (2 m x 4 n), warp tile 64x32.
// ---------------------------------------------------------------------------
__global__ __launch_bounds__(256) void qkv_gemm_tc(const float* __restrict__ A,
                                                   const float* __restrict__ W) {
    constexpr int LDA = 40;    // 32 + 8 pad
    constexpr int LDB = 136;   // 128 + 8 pad
    __shared__ float As[128 * LDA];
    __shared__ float Bs[32 * LDB];

    const int tid = threadIdx.x;
    const int wid = tid >> 5;
    const int wm = wid & 1;    // 0..1
    const int wn = wid >> 1;   // 0..3
    const int bx = blockIdx.x; // N tile (24)
    const int by = blockIdx.y; // M tile (64)

    wmma::fragment<wmma::accumulator, 16, 16, 8, float> acc[4][2];
#pragma unroll
    for (int i = 0; i < 4; i++)
#pragma unroll
        for (int j = 0; j < 2; j++) wmma::fill_fragment(acc[i][j], 0.0f);

    for (int k0 = 0; k0 < DIM; k0 += 32) {
        // fill A tile 128x32 (tf32-rounded)
#pragma unroll
        for (int e = tid; e < 128 * 8; e += 256) {
            int r = e >> 3;
            int c4 = (e & 7) * 4;
            float4 v = *(const float4*)&A[(long)(by * 128 + r) * DIM + k0 + c4];
            float4 t = make_float4(to_tf32(v.x), to_tf32(v.y), to_tf32(v.z), to_tf32(v.w));
            *(float4*)&As[r * LDA + c4] = t;
        }
        // fill B tile 32x128
#pragma unroll
        for (int e = tid; e < 32 * 32; e += 256) {
            int r = e >> 5;
            int c4 = (e & 31) * 4;
            float4 v = *(const float4*)&W[(long)(k0 + r) * QKVC + bx * 128 + c4];
            float4 t = make_float4(to_tf32(v.x), to_tf32(v.y), to_tf32(v.z), to_tf32(v.w));
            *(float4*)&Bs[r * LDB + c4] = t;
        }
        __syncthreads();

#pragma unroll
        for (int kk = 0; kk < 4; ++kk) {
            wmma::fragment<wmma::matrix_a, 16, 16, 8, wmma::precision::tf32, wmma::row_major> af[4];
            wmma::fragment<wmma::matrix_b, 16, 16, 8, wmma::precision::tf32, wmma::row_major> bf[2];
#pragma unroll
            for (int i = 0; i < 4; i++)
                wmma::load_matrix_sync(af[i], &As[(wm * 64 + i * 16) * LDA + kk * 8], LDA);
#pragma unroll
            for (int j = 0; j < 2; j++)
                wmma::load_matrix_sync(bf[j], &Bs[(kk * 8) * LDB + wn * 32 + j * 16], LDB);
#pragma unroll
            for (int i = 0; i < 4; i++)
#pragma unroll
                for (int j = 0; j < 2; j++)
                    wmma::mma_sync(acc[i][j], af[i], bf[j], acc[i][j]);
        }
        __syncthreads();
    }

#pragma unroll
    for (int i = 0; i < 4; i++) {
#pragma unroll
        for (int j = 0; j < 2; j++) {
            long row = by * 128 + wm * 64 + i * 16;
            long col = bx * 128 + wn * 32 + j * 16;
            wmma::store_matrix_sync(&g_qkv[row * QKVC + col], acc[i][j], QKVC,
                                    wmma::mem_row_major);
        }
    }
}

// ---------------------------------------------------------------------------
// Kernel 2: flash attention, tf32 mma.sync, fp32 accumulation.
// grid (N/64, HEADS, B), 128 threads (4 warps). Warp w owns 16 query rows.
// ---------------------------------------------------------------------------
#define LQ 68   // stride for Qs/Ks/Ps  (68 % 32 == 4  -> conflict-free A/B row loads)
#define LV 72   // stride for Vs        (72 % 32 == 8  -> conflict-free V B loads)

__global__ __launch_bounds__(128) void attn_tc(const float* __restrict__ qkv,
                                               float* __restrict__ out) {
    extern __shared__ float sm[];
    float* Qs = sm;                     // 64 x LQ
    float* Ks = Qs + 64 * LQ;           // 64 x LQ
    float* Vs = Ks + 64 * LQ;           // 64 x LV
    float* Ps = Vs + 64 * LV;           // 64 x LQ (warp w -> rows 16w..16w+15)

    const int i0 = blockIdx.x * 64;
    const int h = blockIdx.y;
    const int b = blockIdx.z;
    const int tid = threadIdx.x;
    const int lane = tid & 31;
    const int wid = tid >> 5;
    const int g = lane >> 2;   // 0..7
    const int j = lane & 3;    // 0..3

    const long base = (long)b * NN * QKVC + (long)h * DH;

    // load Q tile (pre-scaled by dk^-1/2 = 0.125, tf32-rounded)
#pragma unroll
    for (int e = tid; e < 64 * 16; e += 128) {
        int r = e >> 4;
        int c4 = (e & 15) * 4;
        float4 v = *(const float4*)&qkv[base + (long)(i0 + r) * QKVC + c4];
        float4 t = make_float4(to_tf32(v.x * 0.125f), to_tf32(v.y * 0.125f),
                               to_tf32(v.z * 0.125f), to_tf32(v.w * 0.125f));
        *(float4*)&Qs[r * LQ + c4] = t;
    }

    float m_i[2] = {-1e30f, -1e30f};
    float l_i[2] = {0.f, 0.f};
    float o[8][4];
#pragma unroll
    for (int nt = 0; nt < 8; nt++)
#pragma unroll
        for (int c = 0; c < 4; c++) o[nt][c] = 0.f;

    for (int t = 0; t < NN / 64; ++t) {
        __syncthreads();
        // load K, V tiles (tf32-rounded)
#pragma unroll
        for (int e = tid; e < 64 * 16; e += 128) {
            int r = e >> 4;
            int c4 = (e & 15) * 4;
            long gofs = base + (long)(t * 64 + r) * QKVC + c4;
            float4 kv = *(const float4*)&qkv[gofs + INNER];
            *(float4*)&Ks[r * LQ + c4] = make_float4(to_tf32(kv.x), to_tf32(kv.y),
                                                     to_tf32(kv.z), to_tf32(kv.w));
            float4 vv = *(const float4*)&qkv[gofs + 2 * INNER];
            *(float4*)&Vs[r * LV + c4] = make_float4(to_tf32(vv.x), to_tf32(vv.y),
                                                     to_tf32(vv.z), to_tf32(vv.w));
        }
        __syncthreads();

        // ---- S = Q K^T : warp computes 16 x 64 in 8 n-tiles of m16n8 ----
        float s[8][4];
#pragma unroll
        for (int nt = 0; nt < 8; nt++)
#pragma unroll
            for (int c = 0; c < 4; c++) s[nt][c] = 0.f;

#pragma unroll
        for (int k0 = 0; k0 < DH; k0 += 8) {
            const float* Qr = Qs + (wid * 16) * LQ + k0;
            unsigned a0 = __float_as_uint(Qr[(g)     * LQ + j]);
            unsigned a1 = __float_as_uint(Qr[(g + 8) * LQ + j]);
            unsigned a2 = __float_as_uint(Qr[(g)     * LQ + j + 4]);
            unsigned a3 = __float_as_uint(Qr[(g + 8) * LQ + j + 4]);
#pragma unroll
            for (int nt = 0; nt < 8; nt++) {
                unsigned b0 = __float_as_uint(Ks[(nt * 8 + g) * LQ + k0 + j]);
                unsigned b1 = __float_as_uint(Ks[(nt * 8 + g) * LQ + k0 + j + 4]);
                mma_tf32(s[nt], a0, a1, a2, a3, b0, b1);
            }
        }

        // ---- online softmax (rows g and g+8 of this warp's 16) ----
#pragma unroll
        for (int half = 0; half < 2; ++half) {
            float mt = -1e30f;
#pragma unroll
            for (int nt = 0; nt < 8; nt++)
                mt = fmaxf(mt, fmaxf(s[nt][2 * half], s[nt][2 * half + 1]));
            mt = fmaxf(mt, __shfl_xor_sync(0xffffffffu, mt, 1));
            mt = fmaxf(mt, __shfl_xor_sync(0xffffffffu, mt, 2));
            float mnew = fmaxf(m_i[half], mt);
            float corr = __expf(m_i[half] - mnew);
            m_i[half] = mnew;
            float ls = 0.f;
            int prow = wid * 16 + g + 8 * half;
#pragma unroll
            for (int nt = 0; nt < 8; nt++) {
                float p0 = __expf(s[nt][2 * half]     - mnew);
                float p1 = __expf(s[nt][2 * half + 1] - mnew);
                ls += p0 + p1;
                *(float2*)&Ps[prow * LQ + nt * 8 + 2 * j] =
                    make_float2(to_tf32(p0), to_tf32(p1));
            }
            ls += __shfl_xor_sync(0xffffffffu, ls, 1);
            ls += __shfl_xor_sync(0xffffffffu, ls, 2);
            l_i[half] = l_i[half] * corr + ls;
#pragma unroll
            for (int nt = 0; nt < 8; nt++) {
                o[nt][2 * half]     *= corr;
                o[nt][2 * half + 1] *= corr;
            }
        }
        __syncwarp();

        // ---- O += P V : k over 64 keys ----
#pragma unroll
        for (int k0 = 0; k0 < 64; k0 += 8) {
            const float* Pr = Ps + (wid * 16) * LQ + k0;
            unsigned a0 = __float_as_uint(Pr[(g)     * LQ + j]);
            unsigned a1 = __float_as_uint(Pr[(g + 8) * LQ + j]);
            unsigned a2 = __float_as_uint(Pr[(g)     * LQ + j + 4]);
            unsigned a3 = __float_as_uint(Pr[(g + 8) * LQ + j + 4]);
#pragma unroll
            for (int nt = 0; nt < 8; nt++) {
                unsigned b0 = __float_as_uint(Vs[(k0 + j)     * LV + nt * 8 + g]);
                unsigned b1 = __float_as_uint(Vs[(k0 + j + 4) * LV + nt * 8 + g]);
                mma_tf32(o[nt], a0, a1, a2, a3, b0, b1);
            }
        }
        __syncwarp();
    }

    // epilogue
#pragma unroll
    for (int half = 0; half < 2; ++half) {
        float inv = 1.f / l_i[half];
        long row = (long)b * NN + i0 + wid * 16 + g + 8 * half;
#pragma unroll
        for (int nt = 0; nt < 8; nt++) {
            long col = (long)h * DH + nt * 8 + 2 * j;
            *(float2*)&out[row * INNER + col] =
                make_float2(o[nt][2 * half] * inv, o[nt][2 * half + 1] * inv);
        }
    }
}

// ---------------------------------------------------------------------------
extern "C" void kernel_launch(void* const* d_in, const int* in_sizes, int n_in,
                              void* d_out, int out_size) {
    const float* x = (const float*)d_in[0];
    const float* w = (const float*)d_in[1];
    float* out = (float*)d_out;

    dim3 g1(QKVC / 128, MROWS / 128);
    qkv_gemm_tc<<<g1, 256>>>(x, w);

    int smem = (64 * LQ * 3 + 64 * LV) * (int)sizeof(float);  // 70656 B
    static int configured = 0;
    if (!configured) {
        cudaFuncSetAttribute(attn_tc, cudaFuncAttributeMaxDynamicSharedMemorySize, smem);
        configured = 1;
    }
    float* qkv_ptr = nullptr;
    cudaGetSymbolAddress((void**)&qkv_ptr, g_qkv);
    dim3 g2(NN / 64, HEADS, BB);
    attn_tc<<<g2, 128, smem>>>(qkv_ptr, out);
}

// round 5
// speedup vs baseline: 3.2169x; 1.2316x over previous
#include <cuda_runtime.h>
#include <cuda_bf16.h>

// Problem constants
#define BB   4
#define NN   2048
#define DIM  1024
#define HEADS 16
#define DH   64
#define INNER 1024          // HEADS*DH
#define QKVC 3072           // 3*INNER
#define MROWS (BB*NN)       // 8192

// Scratch for qkv = x @ w_qkv  [8192,3072], tf32-rounded values stored as fp32
__device__ float g_qkv[(long)MROWS * QKVC];

// ---------------------------------------------------------------------------
__device__ __forceinline__ float to_tf32(float x) {
    unsigned u;
    asm("cvt.rna.tf32.f32 %0, %1;" : "=r"(u) : "f"(x));
    return __uint_as_float(u);
}
__device__ __forceinline__ unsigned fu(float x) { return __float_as_uint(x); }

__device__ __forceinline__ void mma_tf32(float c[4],
                                         unsigned a0, unsigned a1, unsigned a2, unsigned a3,
                                         unsigned b0, unsigned b1) {
    asm volatile(
        "mma.sync.aligned.m16n8k8.row.col.f32.tf32.tf32.f32 "
        "{%0,%1,%2,%3}, {%4,%5,%6,%7}, {%8,%9}, {%0,%1,%2,%3};"
        : "+f"(c[0]), "+f"(c[1]), "+f"(c[2]), "+f"(c[3])
        : "r"(a0), "r"(a1), "r"(a2), "r"(a3), "r"(b0), "r"(b1));
}

// ---------------------------------------------------------------------------
// Kernel 1: QKV GEMM  C[8192,3072] = A[8192,1024] @ W[1024,3072], tf32 mma.
// CTA 128x128, BK=32, double-buffered smem, 8 warps (2m x 4n), warp 64x32.
// ---------------------------------------------------------------------------
#define LDA_G 36    // 36 % 32 == 4  -> A frag LDS.32 conflict-free (4g+j)
#define LDB_G 136   // 136 % 32 == 8 -> B frag LDS.32 conflict-free (8j+g)

__global__ __launch_bounds__(256, 2) void qkv_gemm_tc(const float* __restrict__ A,
                                                      const float* __restrict__ W) {
    extern __shared__ float smg[];
    float* As = smg;                    // 2 x 128 x 36
    float* Bs = smg + 2 * 128 * LDA_G;  // 2 x 32 x 136

    const int tid = threadIdx.x;
    const int lane = tid & 31;
    const int wid = tid >> 5;
    const int g = lane >> 2, j = lane & 3;
    const int wm = wid & 1, wn = wid >> 1;
    const int bx = blockIdx.x, by = blockIdx.y;

    const float* Ag = A + (long)(by * 128) * DIM;
    const float* Wg = W + bx * 128;

    float acc[4][4][4];
#pragma unroll
    for (int i = 0; i < 4; i++)
#pragma unroll
        for (int nt = 0; nt < 4; nt++)
#pragma unroll
            for (int c = 0; c < 4; c++) acc[i][nt][c] = 0.f;

    // fill stage 0
    {
#pragma unroll
        for (int it = 0; it < 4; ++it) {
            int e = tid + it * 256;
            int r = e >> 3, c4 = (e & 7) * 4;
            float4 v = *(const float4*)&Ag[(long)r * DIM + c4];
            *(float4*)&As[r * LDA_G + c4] =
                make_float4(to_tf32(v.x), to_tf32(v.y), to_tf32(v.z), to_tf32(v.w));
        }
#pragma unroll
        for (int it = 0; it < 4; ++it) {
            int e = tid + it * 256;
            int r = e >> 5, c4 = (e & 31) * 4;
            float4 v = *(const float4*)&Wg[(long)r * QKVC + c4];
            *(float4*)&Bs[r * LDB_G + c4] =
                make_float4(to_tf32(v.x), to_tf32(v.y), to_tf32(v.z), to_tf32(v.w));
        }
    }
    __syncthreads();

    float4 pa[4], pb[4];
    for (int step = 0; step < DIM / 32; ++step) {
        const int s = step & 1;
        const float* Ac = As + s * 128 * LDA_G;
        const float* Bc = Bs + s * 32 * LDB_G;

        if (step < DIM / 32 - 1) {
            int k0g = (step + 1) * 32;
#pragma unroll
            for (int it = 0; it < 4; ++it) {
                int e = tid + it * 256;
                int r = e >> 3, c4 = (e & 7) * 4;
                pa[it] = *(const float4*)&Ag[(long)r * DIM + k0g + c4];
            }
#pragma unroll
            for (int it = 0; it < 4; ++it) {
                int e = tid + it * 256;
                int r = e >> 5, c4 = (e & 31) * 4;
                pb[it] = *(const float4*)&Wg[(long)(k0g + r) * QKVC + c4];
            }
        }

#pragma unroll
        for (int kk = 0; kk < 32; kk += 8) {
            float a[4][4];
#pragma unroll
            for (int i = 0; i < 4; i++) {
                const float* Ar = Ac + (wm * 64 + i * 16) * LDA_G + kk;
                a[i][0] = Ar[g * LDA_G + j];
                a[i][1] = Ar[(g + 8) * LDA_G + j];
                a[i][2] = Ar[g * LDA_G + j + 4];
                a[i][3] = Ar[(g + 8) * LDA_G + j + 4];
            }
#pragma unroll
            for (int nt = 0; nt < 4; nt++) {
                const float* Br = Bc + kk * LDB_G + wn * 32 + nt * 8 + g;
                unsigned b0 = fu(Br[j * LDB_G]);
                unsigned b1 = fu(Br[(j + 4) * LDB_G]);
#pragma unroll
                for (int i = 0; i < 4; i++)
                    mma_tf32(acc[i][nt], fu(a[i][0]), fu(a[i][1]), fu(a[i][2]),
                             fu(a[i][3]), b0, b1);
            }
        }

        if (step < DIM / 32 - 1) {
            float* An = As + (s ^ 1) * 128 * LDA_G;
            float* Bn = Bs + (s ^ 1) * 32 * LDB_G;
#pragma unroll
            for (int it = 0; it < 4; ++it) {
                int e = tid + it * 256;
                int r = e >> 3, c4 = (e & 7) * 4;
                *(float4*)&An[r * LDA_G + c4] =
                    make_float4(to_tf32(pa[it].x), to_tf32(pa[it].y),
                                to_tf32(pa[it].z), to_tf32(pa[it].w));
            }
#pragma unroll
            for (int it = 0; it < 4; ++it) {
                int e = tid + it * 256;
                int r = e >> 5, c4 = (e & 31) * 4;
                *(float4*)&Bn[r * LDB_G + c4] =
                    make_float4(to_tf32(pb[it].x), to_tf32(pb[it].y),
                                to_tf32(pb[it].z), to_tf32(pb[it].w));
            }
        }
        __syncthreads();
    }

    // epilogue: round to tf32, store
#pragma unroll
    for (int i = 0; i < 4; i++) {
#pragma unroll
        for (int nt = 0; nt < 4; nt++) {
            long row = by * 128 + wm * 64 + i * 16 + g;
            long col = bx * 128 + wn * 32 + nt * 8 + 2 * j;
            *(float2*)&g_qkv[row * QKVC + col] =
                make_float2(to_tf32(acc[i][nt][0]), to_tf32(acc[i][nt][1]));
            *(float2*)&g_qkv[(row + 8) * QKVC + col] =
                make_float2(to_tf32(acc[i][nt][2]), to_tf32(acc[i][nt][3]));
        }
    }
}

// ---------------------------------------------------------------------------
// Kernel 2: flash attention, tf32 mma, 128-query tile, 8 warps.
// Pair-permuted smem layouts: cols (j, j+4) of each 8-group stored adjacent
// so A/B fragments load as LDS.64.  sigma(c) = (c&~7) + 2*(c&3) + ((c>>2)&1)
// ---------------------------------------------------------------------------
#define LQK 72   // 72 % 32 == 8 -> paired LDS.64 conflict-free per 16-lane phase
#define LPP 68   // 68 % 32 == 4 -> scalar P LDS.32 conflict-free (4g+j)
#define BRQ 128
#define BCK 64

__global__ __launch_bounds__(256, 2) void attn_tc(const float* __restrict__ qkv,
                                                  float* __restrict__ out) {
    extern __shared__ float sm[];
    float* Qs = sm;                   // 128 x 72 (sigma-permuted cols)
    float* Ks = Qs + BRQ * LQK;       // 64 x 72  (n-major, sigma cols)
    float* Vt = Ks + BCK * LQK;       // 64 x 72  (d-major, sigma on key idx)
    float* Ps = Vt + BCK * LQK;       // 128 x 68 (plain)

    const int i0 = blockIdx.x * BRQ;
    const int h = blockIdx.y;
    const int b = blockIdx.z;
    const int tid = threadIdx.x;
    const int lane = tid & 31;
    const int wid = tid >> 5;
    const int g = lane >> 2, j = lane & 3;
    const int q0 = wid * 16;

    const long base = (long)b * NN * QKVC + (long)h * DH;

    // Q fill: scaled by 0.125 (exact pow2; values already tf32 from GEMM)
#pragma unroll
    for (int e = tid; e < BRQ * 16; e += 256) {
        int r = e >> 4;
        int c4 = (e & 15) * 4;
        float4 v = *(const float4*)&qkv[base + (long)(i0 + r) * QKVC + c4];
        int p = (c4 & ~7) + ((c4 >> 2) & 1);   // + 2*i for component i
        float* Qr = Qs + r * LQK + p;
        Qr[0] = v.x * 0.125f; Qr[2] = v.y * 0.125f;
        Qr[4] = v.z * 0.125f; Qr[6] = v.w * 0.125f;
    }

    float m_i[2] = {-1e30f, -1e30f};
    float l_i[2] = {0.f, 0.f};
    float o[8][4];
#pragma unroll
    for (int nt = 0; nt < 8; nt++)
#pragma unroll
        for (int c = 0; c < 4; c++) o[nt][c] = 0.f;

    for (int t = 0; t < NN / BCK; ++t) {
        __syncthreads();
        // K fill: [key n][sigma(dim)]
#pragma unroll
        for (int e = tid; e < BCK * 16; e += 256) {
            int r = e >> 4;
            int c4 = (e & 15) * 4;
            float4 v = *(const float4*)&qkv[base + (long)(t * BCK + r) * QKVC + INNER + c4];
            int p = (c4 & ~7) + ((c4 >> 2) & 1);
            float* Kr = Ks + r * LQK + p;
            Kr[0] = v.x; Kr[2] = v.y; Kr[4] = v.z; Kr[6] = v.w;
        }
        // V fill transposed: Vt[dim d][sigma(key r)]
#pragma unroll
        for (int e = tid; e < BCK * 16; e += 256) {
            int r = e & 63;
            int c4 = (e >> 6) * 4;
            float4 v = *(const float4*)&qkv[base + (long)(t * BCK + r) * QKVC + 2 * INNER + c4];
            int sr = (r & ~7) + 2 * (r & 3) + ((r >> 2) & 1);
            Vt[(c4 + 0) * LQK + sr] = v.x;
            Vt[(c4 + 1) * LQK + sr] = v.y;
            Vt[(c4 + 2) * LQK + sr] = v.z;
            Vt[(c4 + 3) * LQK + sr] = v.w;
        }
        __syncthreads();

        // ---- S = Q K^T : 16 x 64 per warp ----
        float s[8][4];
#pragma unroll
        for (int nt = 0; nt < 8; nt++)
#pragma unroll
            for (int c = 0; c < 4; c++) s[nt][c] = 0.f;

#pragma unroll
        for (int k0 = 0; k0 < DH; k0 += 8) {
            const float* Qr = Qs + q0 * LQK + k0 + 2 * j;
            float2 a02 = *(const float2*)&Qr[g * LQK];        // (col j, col j+4)
            float2 a13 = *(const float2*)&Qr[(g + 8) * LQK];
#pragma unroll
            for (int nt = 0; nt < 8; nt++) {
                float2 bb = *(const float2*)&Ks[(nt * 8 + g) * LQK + k0 + 2 * j];
                mma_tf32(s[nt], fu(a02.x), fu(a13.x), fu(a02.y), fu(a13.y),
                         fu(bb.x), fu(bb.y));
            }
        }

        // ---- online softmax ----
#pragma unroll
        for (int half = 0; half < 2; ++half) {
            float mt = -1e30f;
#pragma unroll
            for (int nt = 0; nt < 8; nt++)
                mt = fmaxf(mt, fmaxf(s[nt][2 * half], s[nt][2 * half + 1]));
            mt = fmaxf(mt, __shfl_xor_sync(0xffffffffu, mt, 1));
            mt = fmaxf(mt, __shfl_xor_sync(0xffffffffu, mt, 2));
            float mnew = fmaxf(m_i[half], mt);
            float corr = __expf(m_i[half] - mnew);
            m_i[half] = mnew;
            float ls = 0.f;
            int prow = q0 + g + 8 * half;
#pragma unroll
            for (int nt = 0; nt < 8; nt++) {
                float p0 = __expf(s[nt][2 * half] - mnew);
                float p1 = __expf(s[nt][2 * half + 1] - mnew);
                ls += p0 + p1;
                *(float2*)&Ps[prow * LPP + nt * 8 + 2 * j] =
                    make_float2(to_tf32(p0), to_tf32(p1));
            }
            ls += __shfl_xor_sync(0xffffffffu, ls, 1);
            ls += __shfl_xor_sync(0xffffffffu, ls, 2);
            l_i[half] = l_i[half] * corr + ls;
#pragma unroll
            for (int nt = 0; nt < 8; nt++) {
                o[nt][2 * half]     *= corr;
                o[nt][2 * half + 1] *= corr;
            }
        }
        __syncwarp();

        // ---- O += P V ----
#pragma unroll
        for (int k0 = 0; k0 < BCK; k0 += 8) {
            const float* Pr = Ps + q0 * LPP + k0;
            unsigned a0 = fu(Pr[g * LPP + j]);
            unsigned a1 = fu(Pr[(g + 8) * LPP + j]);
            unsigned a2 = fu(Pr[g * LPP + j + 4]);
            unsigned a3 = fu(Pr[(g + 8) * LPP + j + 4]);
#pragma unroll
            for (int nt = 0; nt < 8; nt++) {
                float2 bb = *(const float2*)&Vt[(nt * 8 + g) * LQK + k0 + 2 * j];
                mma_tf32(o[nt], a0, a1, a2, a3, fu(bb.x), fu(bb.y));
            }
        }
        __syncwarp();
    }

    // epilogue
#pragma unroll
    for (int half = 0; half < 2; ++half) {
        float inv = 1.f / l_i[half];
        long row = (long)b * NN + i0 + q0 + g + 8 * half;
#pragma unroll
        for (int nt = 0; nt < 8; nt++) {
            long col = (long)h * DH + nt * 8 + 2 * j;
            *(float2*)&out[row * INNER + col] =
                make_float2(o[nt][2 * half] * inv, o[nt][2 * half + 1] * inv);
        }
    }
}

// ---------------------------------------------------------------------------
extern "C" void kernel_launch(void* const* d_in, const int* in_sizes, int n_in,
                              void* d_out, int out_size) {
    const float* x = (const float*)d_in[0];
    const float* w = (const float*)d_in[1];
    float* out = (float*)d_out;

    int smem_g = (2 * 128 * LDA_G + 2 * 32 * LDB_G) * (int)sizeof(float);  // 71680
    int smem_a = (BRQ * LQK + BCK * LQK * 2 + BRQ * LPP) * (int)sizeof(float);  // 108544
    static int configured = 0;
    if (!configured) {
        cudaFuncSetAttribute(qkv_gemm_tc, cudaFuncAttributeMaxDynamicSharedMemorySize, smem_g);
        cudaFuncSetAttribute(attn_tc, cudaFuncAttributeMaxDynamicSharedMemorySize, smem_a);
        configured = 1;
    }

    dim3 g1(QKVC / 128, MROWS / 128);
    qkv_gemm_tc<<<g1, 256, smem_g>>>(x, w);

    float* qkv_ptr = nullptr;
    cudaGetSymbolAddress((void**)&qkv_ptr, g_qkv);
    dim3 g2(NN / BRQ, HEADS, BB);
    attn_tc<<<g2, 256, smem_a>>>(qkv_ptr, out);
}

// round 10
// speedup vs baseline: 3.2495x; 1.0101x over previous
#include <cuda_runtime.h>
#include <cuda_bf16.h>

// Problem constants
#define BB   4
#define NN   2048
#define DIM  1024
#define HEADS 16
#define DH   64
#define INNER 1024          // HEADS*DH
#define QKVC 3072           // 3*INNER
#define MROWS (BB*NN)       // 8192

// Scratch for qkv = x @ w_qkv  [8192,3072], tf32-rounded values stored as fp32
__device__ float g_qkv[(long)MROWS * QKVC];

// ---------------------------------------------------------------------------
__device__ __forceinline__ float to_tf32(float x) {
    unsigned u;
    asm("cvt.rna.tf32.f32 %0, %1;" : "=r"(u) : "f"(x));
    return __uint_as_float(u);
}
__device__ __forceinline__ unsigned fu(float x) { return __float_as_uint(x); }

__device__ __forceinline__ void mma_tf32(float c[4],
                                         unsigned a0, unsigned a1, unsigned a2, unsigned a3,
                                         unsigned b0, unsigned b1) {
    asm volatile(
        "mma.sync.aligned.m16n8k8.row.col.f32.tf32.tf32.f32 "
        "{%0,%1,%2,%3}, {%4,%5,%6,%7}, {%8,%9}, {%0,%1,%2,%3};"
        : "+f"(c[0]), "+f"(c[1]), "+f"(c[2]), "+f"(c[3])
        : "r"(a0), "r"(a1), "r"(a2), "r"(a3), "r"(b0), "r"(b1));
}

// ---------------------------------------------------------------------------
// Kernel 1: QKV GEMM  C[8192,3072] = A[8192,1024] @ W[1024,3072], tf32 mma.
// CTA 128x128, BK=32, double-buffered smem, 8 warps (2m x 4n), warp 64x32.
// (unchanged from R5: 700 -> ~372us)
// ---------------------------------------------------------------------------
#define LDA_G 36    // 36 % 32 == 4  -> A frag LDS.32 conflict-free (4g+j)
#define LDB_G 136   // 136 % 32 == 8 -> B frag LDS.32 conflict-free (8j+g)

__global__ __launch_bounds__(256, 2) void qkv_gemm_tc(const float* __restrict__ A,
                                                      const float* __restrict__ W) {
    extern __shared__ float smg[];
    float* As = smg;                    // 2 x 128 x 36
    float* Bs = smg + 2 * 128 * LDA_G;  // 2 x 32 x 136

    const int tid = threadIdx.x;
    const int lane = tid & 31;
    const int wid = tid >> 5;
    const int g = lane >> 2, j = lane & 3;
    const int wm = wid & 1, wn = wid >> 1;
    const int bx = blockIdx.x, by = blockIdx.y;

    const float* Ag = A + (long)(by * 128) * DIM;
    const float* Wg = W + bx * 128;

    float acc[4][4][4];
#pragma unroll
    for (int i = 0; i < 4; i++)
#pragma unroll
        for (int nt = 0; nt < 4; nt++)
#pragma unroll
            for (int c = 0; c < 4; c++) acc[i][nt][c] = 0.f;

    // fill stage 0
    {
#pragma unroll
        for (int it = 0; it < 4; ++it) {
            int e = tid + it * 256;
            int r = e >> 3, c4 = (e & 7) * 4;
            float4 v = *(const float4*)&Ag[(long)r * DIM + c4];
            *(float4*)&As[r * LDA_G + c4] =
                make_float4(to_tf32(v.x), to_tf32(v.y), to_tf32(v.z), to_tf32(v.w));
        }
#pragma unroll
        for (int it = 0; it < 4; ++it) {
            int e = tid + it * 256;
            int r = e >> 5, c4 = (e & 31) * 4;
            float4 v = *(const float4*)&Wg[(long)r * QKVC + c4];
            *(float4*)&Bs[r * LDB_G + c4] =
                make_float4(to_tf32(v.x), to_tf32(v.y), to_tf32(v.z), to_tf32(v.w));
        }
    }
    __syncthreads();

    float4 pa[4], pb[4];
    for (int step = 0; step < DIM / 32; ++step) {
        const int s = step & 1;
        const float* Ac = As + s * 128 * LDA_G;
        const float* Bc = Bs + s * 32 * LDB_G;

        if (step < DIM / 32 - 1) {
            int k0g = (step + 1) * 32;
#pragma unroll
            for (int it = 0; it < 4; ++it) {
                int e = tid + it * 256;
                int r = e >> 3, c4 = (e & 7) * 4;
                pa[it] = *(const float4*)&Ag[(long)r * DIM + k0g + c4];
            }
#pragma unroll
            for (int it = 0; it < 4; ++it) {
                int e = tid + it * 256;
                int r = e >> 5, c4 = (e & 31) * 4;
                pb[it] = *(const float4*)&Wg[(long)(k0g + r) * QKVC + c4];
            }
        }

#pragma unroll
        for (int kk = 0; kk < 32; kk += 8) {
            float a[4][4];
#pragma unroll
            for (int i = 0; i < 4; i++) {
                const float* Ar = Ac + (wm * 64 + i * 16) * LDA_G + kk;
                a[i][0] = Ar[g * LDA_G + j];
                a[i][1] = Ar[(g + 8) * LDA_G + j];
                a[i][2] = Ar[g * LDA_G + j + 4];
                a[i][3] = Ar[(g + 8) * LDA_G + j + 4];
            }
#pragma unroll
            for (int nt = 0; nt < 4; nt++) {
                const float* Br = Bc + kk * LDB_G + wn * 32 + nt * 8 + g;
                unsigned b0 = fu(Br[j * LDB_G]);
                unsigned b1 = fu(Br[(j + 4) * LDB_G]);
#pragma unroll
                for (int i = 0; i < 4; i++)
                    mma_tf32(acc[i][nt], fu(a[i][0]), fu(a[i][1]), fu(a[i][2]),
                             fu(a[i][3]), b0, b1);
            }
        }

        if (step < DIM / 32 - 1) {
            float* An = As + (s ^ 1) * 128 * LDA_G;
            float* Bn = Bs + (s ^ 1) * 32 * LDB_G;
#pragma unroll
            for (int it = 0; it < 4; ++it) {
                int e = tid + it * 256;
                int r = e >> 3, c4 = (e & 7) * 4;
                *(float4*)&An[r * LDA_G + c4] =
                    make_float4(to_tf32(pa[it].x), to_tf32(pa[it].y),
                                to_tf32(pa[it].z), to_tf32(pa[it].w));
            }
#pragma unroll
            for (int it = 0; it < 4; ++it) {
                int e = tid + it * 256;
                int r = e >> 5, c4 = (e & 31) * 4;
                *(float4*)&Bn[r * LDB_G + c4] =
                    make_float4(to_tf32(pb[it].x), to_tf32(pb[it].y),
                                to_tf32(pb[it].z), to_tf32(pb[it].w));
            }
        }
        __syncthreads();
    }

    // epilogue: round to tf32, store
#pragma unroll
    for (int i = 0; i < 4; i++) {
#pragma unroll
        for (int nt = 0; nt < 4; nt++) {
            long row = by * 128 + wm * 64 + i * 16 + g;
            long col = bx * 128 + wn * 32 + nt * 8 + 2 * j;
            *(float2*)&g_qkv[row * QKVC + col] =
                make_float2(to_tf32(acc[i][nt][0]), to_tf32(acc[i][nt][1]));
            *(float2*)&g_qkv[(row + 8) * QKVC + col] =
                make_float2(to_tf32(acc[i][nt][2]), to_tf32(acc[i][nt][3]));
        }
    }
}

// ---------------------------------------------------------------------------
// Kernel 2: flash attention, tf32 mma, 128-query tile, 4 warps.
// Warp tile 32x64 (2 m-tiles): every K/V B-fragment feeds 2 mma -> LDS
// bytes/mma drop from 1.25 to 0.75 LDS.64 (crossbar-bound kernel).
// Pair-permuted smem: sigma(c) = (c&~7) + 2*(c&3) + ((c>>2)&1)
// ---------------------------------------------------------------------------
#define LQK 72   // 72 % 32 == 8 -> paired LDS.64 conflict-free per 16-lane phase
#define LPP 68   // 68 % 32 == 4 -> scalar P LDS.32 conflict-free (4g+j)
#define BRQ 128
#define BCK 64

__global__ __launch_bounds__(128, 2) void attn_tc(const float* __restrict__ qkv,
                                                  float* __restrict__ out) {
    extern __shared__ float sm[];
    float* Qs = sm;                   // 128 x 72 (sigma-permuted cols)
    float* Ks = Qs + BRQ * LQK;       // 64 x 72  (n-major, sigma cols)
    float* Vt = Ks + BCK * LQK;       // 64 x 72  (d-major, sigma on key idx)
    float* Ps = Vt + BCK * LQK;       // 128 x 68 (plain)

    const int i0 = blockIdx.x * BRQ;
    const int h = blockIdx.y;
    const int b = blockIdx.z;
    const int tid = threadIdx.x;
    const int lane = tid & 31;
    const int wid = tid >> 5;          // 0..3
    const int g = lane >> 2, j = lane & 3;
    const int q0 = wid * 32;           // warp owns 32 query rows (2 m-tiles)

    const long base = (long)b * NN * QKVC + (long)h * DH;

    // Q fill: scaled by 0.125 (exact pow2; values already tf32 from GEMM)
#pragma unroll
    for (int e = tid; e < BRQ * 16; e += 128) {
        int r = e >> 4;
        int c4 = (e & 15) * 4;
        float4 v = *(const float4*)&qkv[base + (long)(i0 + r) * QKVC + c4];
        int p = (c4 & ~7) + ((c4 >> 2) & 1);   // + 2*i for component i
        float* Qr = Qs + r * LQK + p;
        Qr[0] = v.x * 0.125f; Qr[2] = v.y * 0.125f;
        Qr[4] = v.z * 0.125f; Qr[6] = v.w * 0.125f;
    }

    float m_i[2][2], l_i[2][2];
    float o[2][8][4];
#pragma unroll
    for (int mt = 0; mt < 2; mt++) {
        m_i[mt][0] = m_i[mt][1] = -1e30f;
        l_i[mt][0] = l_i[mt][1] = 0.f;
#pragma unroll
        for (int nt = 0; nt < 8; nt++)
#pragma unroll
            for (int c = 0; c < 4; c++) o[mt][nt][c] = 0.f;
    }

    for (int t = 0; t < NN / BCK; ++t) {
        __syncthreads();
        // K fill: [key n][sigma(dim)]
#pragma unroll
        for (int e = tid; e < BCK * 16; e += 128) {
            int r = e >> 4;
            int c4 = (e & 15) * 4;
            float4 v = *(const float4*)&qkv[base + (long)(t * BCK + r) * QKVC + INNER + c4];
            int p = (c4 & ~7) + ((c4 >> 2) & 1);
            float* Kr = Ks + r * LQK + p;
            Kr[0] = v.x; Kr[2] = v.y; Kr[4] = v.z; Kr[6] = v.w;
        }
        // V fill transposed: Vt[dim d][sigma(key r)]
#pragma unroll
        for (int e = tid; e < BCK * 16; e += 128) {
            int r = e & 63;
            int c4 = (e >> 6) * 4;
            float4 v = *(const float4*)&qkv[base + (long)(t * BCK + r) * QKVC + 2 * INNER + c4];
            int sr = (r & ~7) + 2 * (r & 3) + ((r >> 2) & 1);
            Vt[(c4 + 0) * LQK + sr] = v.x;
            Vt[(c4 + 1) * LQK + sr] = v.y;
            Vt[(c4 + 2) * LQK + sr] = v.z;
            Vt[(c4 + 3) * LQK + sr] = v.w;
        }
        __syncthreads();

        // ---- S = Q K^T : 32 x 64 per warp (2 m-tiles share each K frag) ----
        float s[2][8][4];
#pragma unroll
        for (int mt = 0; mt < 2; mt++)
#pragma unroll
            for (int nt = 0; nt < 8; nt++)
#pragma unroll
                for (int c = 0; c < 4; c++) s[mt][nt][c] = 0.f;

#pragma unroll
        for (int k0 = 0; k0 < DH; k0 += 8) {
            float2 aq[2][2];
#pragma unroll
            for (int mt = 0; mt < 2; mt++) {
                const float* Qr = Qs + (q0 + mt * 16) * LQK + k0 + 2 * j;
                aq[mt][0] = *(const float2*)&Qr[g * LQK];        // (col j, col j+4)
                aq[mt][1] = *(const float2*)&Qr[(g + 8) * LQK];
            }
#pragma unroll
            for (int nt = 0; nt < 8; nt++) {
                float2 bb = *(const float2*)&Ks[(nt * 8 + g) * LQK + k0 + 2 * j];
#pragma unroll
                for (int mt = 0; mt < 2; mt++)
                    mma_tf32(s[mt][nt], fu(aq[mt][0].x), fu(aq[mt][1].x),
                             fu(aq[mt][0].y), fu(aq[mt][1].y), fu(bb.x), fu(bb.y));
            }
        }

        // ---- online softmax per m-tile ----
#pragma unroll
        for (int mt = 0; mt < 2; mt++) {
#pragma unroll
            for (int half = 0; half < 2; ++half) {
                float mt_max = -1e30f;
#pragma unroll
                for (int nt = 0; nt < 8; nt++)
                    mt_max = fmaxf(mt_max, fmaxf(s[mt][nt][2 * half], s[mt][nt][2 * half + 1]));
                mt_max = fmaxf(mt_max, __shfl_xor_sync(0xffffffffu, mt_max, 1));
                mt_max = fmaxf(mt_max, __shfl_xor_sync(0xffffffffu, mt_max, 2));
                float mnew = fmaxf(m_i[mt][half], mt_max);
                float corr = __expf(m_i[mt][half] - mnew);
                m_i[mt][half] = mnew;
                float ls = 0.f;
                int prow = q0 + mt * 16 + g + 8 * half;
#pragma unroll
                for (int nt = 0; nt < 8; nt++) {
                    float p0 = __expf(s[mt][nt][2 * half] - mnew);
                    float p1 = __expf(s[mt][nt][2 * half + 1] - mnew);
                    ls += p0 + p1;
                    *(float2*)&Ps[prow * LPP + nt * 8 + 2 * j] =
                        make_float2(to_tf32(p0), to_tf32(p1));
                }
                ls += __shfl_xor_sync(0xffffffffu, ls, 1);
                ls += __shfl_xor_sync(0xffffffffu, ls, 2);
                l_i[mt][half] = l_i[mt][half] * corr + ls;
#pragma unroll
                for (int nt = 0; nt < 8; nt++) {
                    o[mt][nt][2 * half]     *= corr;
                    o[mt][nt][2 * half + 1] *= corr;
                }
            }
        }
        __syncwarp();

        // ---- O += P V : 32 x 64 per warp (2 m-tiles share each V frag) ----
#pragma unroll
        for (int k0 = 0; k0 < BCK; k0 += 8) {
            unsigned pa[2][4];
#pragma unroll
            for (int mt = 0; mt < 2; mt++) {
                const float* Pr = Ps + (q0 + mt * 16) * LPP + k0;
                pa[mt][0] = fu(Pr[g * LPP + j]);
                pa[mt][1] = fu(Pr[(g + 8) * LPP + j]);
                pa[mt][2] = fu(Pr[g * LPP + j + 4]);
                pa[mt][3] = fu(Pr[(g + 8) * LPP + j + 4]);
            }
#pragma unroll
            for (int nt = 0; nt < 8; nt++) {
                float2 bb = *(const float2*)&Vt[(nt * 8 + g) * LQK + k0 + 2 * j];
#pragma unroll
                for (int mt = 0; mt < 2; mt++)
                    mma_tf32(o[mt][nt], pa[mt][0], pa[mt][1], pa[mt][2], pa[mt][3],
                             fu(bb.x), fu(bb.y));
            }
        }
        __syncwarp();
    }

    // epilogue
#pragma unroll
    for (int mt = 0; mt < 2; mt++) {
#pragma unroll
        for (int half = 0; half < 2; ++half) {
            float inv = 1.f / l_i[mt][half];
            long row = (long)b * NN + i0 + q0 + mt * 16 + g + 8 * half;
#pragma unroll
            for (int nt = 0; nt < 8; nt++) {
                long col = (long)h * DH + nt * 8 + 2 * j;
                *(float2*)&out[row * INNER + col] =
                    make_float2(o[mt][nt][2 * half] * inv, o[mt][nt][2 * half + 1] * inv);
            }
        }
    }
}

// ---------------------------------------------------------------------------
extern "C" void kernel_launch(void* const* d_in, const int* in_sizes, int n_in,
                              void* d_out, int out_size) {
    const float* x = (const float*)d_in[0];
    const float* w = (const float*)d_in[1];
    float* out = (float*)d_out;

    int smem_g = (2 * 128 * LDA_G + 2 * 32 * LDB_G) * (int)sizeof(float);  // 71680
    int smem_a = (BRQ * LQK + BCK * LQK * 2 + BRQ * LPP) * (int)sizeof(float);  // 108544
    static int configured = 0;
    if (!configured) {
        cudaFuncSetAttribute(qkv_gemm_tc, cudaFuncAttributeMaxDynamicSharedMemorySize, smem_g);
        cudaFuncSetAttribute(attn_tc, cudaFuncAttributeMaxDynamicSharedMemorySize, smem_a);
        configured = 1;
    }

    dim3 g1(QKVC / 128, MROWS / 128);
    qkv_gemm_tc<<<g1, 256, smem_g>>>(x, w);

    float* qkv_ptr = nullptr;
    cudaGetSymbolAddress((void**)&qkv_ptr, g_qkv);
    dim3 g2(NN / BRQ, HEADS, BB);
    attn_tc<<<g2, 128, smem_a>>>(qkv_ptr, out);
}